// round 12
// baseline (speedup 1.0000x reference)
#include <cuda_runtime.h>
#include <cuda_bf16.h>
#include <stdint.h>

// PatchAttention: B=2, C=128, H=W=512, S=16 -> 2048 patches x (L=256, d=128)
// One CTA per patch, 256 threads (8 warps x 32 query rows). Fully fused.
// Q in registers; V in-place over P; weights pre-converted bf16 (swizzled);
// ldsm_x4 B-loads feed 2 MMAs (m=0,1) each -> half the SMEM bytes of R8.

#define SMEM_P     0u        // p^T, later V : [256][128] bf16 swizzled (64 KB)
#define SMEM_K     65536u    // K            : [256][128] bf16 swizzled (64 KB)
#define SMEM_W0    131072u   // Wq stage (32 KB)
#define SMEM_W1    163840u   // Wk stage, later Wo (32 KB)
#define SMEM_W2    196608u   // Wv stage (32 KB)
#define SMEM_Z     0u        // phase-3 Z [128][260] f32 (overlays P,K,W0-head)
#define SMEM_TOTAL 229376u

#define INV_TEMP 0.08838834764831845f  // 1/sqrt(128)

__device__ uint32_t gW[4][8192];  // bf16x2-packed, swizzled: Wq, Wk, Wv, Wo

__device__ __forceinline__ uint32_t pack2bf(float lo, float hi) {
    uint32_t r;
    asm("cvt.rn.bf16x2.f32 %0, %1, %2;" : "=r"(r) : "f"(hi), "f"(lo));
    return r;
}
__device__ __forceinline__ uint16_t bf16b(float v) {
    uint16_t r;
    asm("cvt.rn.bf16.f32 %0, %1;" : "=h"(r) : "f"(v));
    return r;
}
// swizzled address in a matrix of 256B rows (128 bf16); 16B chunk ^= row&7
__device__ __forceinline__ uint32_t mrow(uint32_t base, int row, int chunk) {
    return base + (uint32_t)row * 256u + (uint32_t)(((chunk ^ (row & 7)) << 4));
}
__device__ __forceinline__ void ldsm_x4(uint32_t a, uint32_t r[4]) {
    asm volatile("ldmatrix.sync.aligned.m8n8.x4.shared.b16 {%0,%1,%2,%3}, [%4];"
                 : "=r"(r[0]), "=r"(r[1]), "=r"(r[2]), "=r"(r[3]) : "r"(a));
}
__device__ __forceinline__ void ldsm_x4t(uint32_t a, uint32_t r[4]) {
    asm volatile("ldmatrix.sync.aligned.m8n8.x4.trans.shared.b16 {%0,%1,%2,%3}, [%4];"
                 : "=r"(r[0]), "=r"(r[1]), "=r"(r[2]), "=r"(r[3]) : "r"(a));
}
__device__ __forceinline__ void mma16816(float c[4], const uint32_t a[4],
                                         uint32_t b0, uint32_t b1) {
    asm volatile(
        "mma.sync.aligned.m16n8k16.row.col.f32.bf16.bf16.f32 "
        "{%0,%1,%2,%3},{%4,%5,%6,%7},{%8,%9},{%0,%1,%2,%3};"
        : "+f"(c[0]), "+f"(c[1]), "+f"(c[2]), "+f"(c[3])
        : "r"(a[0]), "r"(a[1]), "r"(a[2]), "r"(a[3]), "r"(b0), "r"(b1));
}
__device__ __forceinline__ void cp16(uint32_t s, const void* g) {
    asm volatile("cp.async.ca.shared.global [%0], [%1], 16;" :: "r"(s), "l"(g));
}
__device__ __forceinline__ void cp_commit() { asm volatile("cp.async.commit_group;"); }
__device__ __forceinline__ void cp_wait_all() { asm volatile("cp.async.wait_group 0;"); }

// ---- prep: fp32 weights -> bf16x2 packed, swizzled, into gW ----------------
__global__ void prep_weights(const float* __restrict__ Wq,
                             const float* __restrict__ Wk,
                             const float* __restrict__ Wv,
                             const float* __restrict__ Wo) {
    const float* Ws[4] = {Wq, Wk, Wv, Wo};
    int t = blockIdx.x * 256 + threadIdx.x;  // 8192 threads
#pragma unroll
    for (int i = 0; i < 4; i++) {
        int idx = t + i * 8192;              // 32768 total u32 slots
        int w = idx >> 13, rem = idx & 8191;
        int d = rem >> 6, j = rem & 63;      // j = column-pair index
        float2 v = *reinterpret_cast<const float2*>(Ws[w] + d * 128 + 2 * j);
        gW[w][d * 64 + (((j >> 2) ^ (d & 7)) << 2) + (j & 3)] = pack2bf(v.x, v.y);
    }
}

// projection: dst(own 32 rows) = P(own rows) @ W^T + bias, bf16 -> SMEM
__device__ __forceinline__ void proj_store(char* smem, uint32_t sb,
                                           uint32_t wOff, uint32_t dOff,
                                           const float* __restrict__ bias,
                                           int tm, int lane) {
    float acc[16][2][4];
#pragma unroll
    for (int nt = 0; nt < 16; nt++)
#pragma unroll
        for (int m = 0; m < 2; m++)
#pragma unroll
            for (int j = 0; j < 4; j++) acc[nt][m][j] = 0.f;
#pragma unroll
    for (int kt = 0; kt < 8; kt++) {
        uint32_t a0[4], a1[4];
        ldsm_x4(mrow(sb + SMEM_P, tm +      (lane & 15), kt * 2 + (lane >> 4)), a0);
        ldsm_x4(mrow(sb + SMEM_P, tm + 16 + (lane & 15), kt * 2 + (lane >> 4)), a1);
#pragma unroll
        for (int np = 0; np < 8; np++) {
            uint32_t wb[4];   // [0]=b0 lo-nt, [1]=b0 hi-nt, [2]=b1 lo-nt, [3]=b1 hi-nt
            ldsm_x4(mrow(sb + wOff, np * 16 + (lane & 15), kt * 2 + (lane >> 4)), wb);
            mma16816(acc[2*np][0],   a0, wb[0], wb[2]);
            mma16816(acc[2*np+1][0], a0, wb[1], wb[3]);
            mma16816(acc[2*np][1],   a1, wb[0], wb[2]);
            mma16816(acc[2*np+1][1], a1, wb[1], wb[3]);
        }
    }
    const int g  = lane >> 2;
    const int c4 = (lane & 3) << 1;
#pragma unroll
    for (int nt = 0; nt < 16; nt++) {
        float blo = __ldg(bias + nt * 8 + c4);
        float bhi = __ldg(bias + nt * 8 + c4 + 1);
#pragma unroll
        for (int m = 0; m < 2; m++) {
            int r = tm + m * 16 + g;
            uint32_t lo = pack2bf(acc[nt][m][0] + blo, acc[nt][m][1] + bhi);
            uint32_t hi = pack2bf(acc[nt][m][2] + blo, acc[nt][m][3] + bhi);
            uint32_t cb = (uint32_t)(((nt ^ (r & 7)) << 4) + c4 * 2);
            *reinterpret_cast<uint32_t*>(smem + dOff + (uint32_t)r * 256u + cb) = lo;
            *reinterpret_cast<uint32_t*>(smem + dOff + (uint32_t)(r + 8) * 256u + cb) = hi;
        }
    }
}

__global__ void __launch_bounds__(256, 1)
PatchAttention_24902220382269_kernel(
    const float* __restrict__ x,
    const float* __restrict__ bq, const float* __restrict__ bk,
    const float* __restrict__ bv, const float* __restrict__ bo,
    float* __restrict__ out)
{
    extern __shared__ char smem[];
    const uint32_t sb = (uint32_t)__cvta_generic_to_shared(smem);
    const int tid  = threadIdx.x;
    const int lane = tid & 31;
    const int warp = tid >> 5;
    const int tm   = warp * 32;          // 32 query rows per warp

    const int pid   = blockIdx.x;
    const int bN    = pid >> 10;
    const int ph    = (pid >> 5) & 31;
    const int pw    = pid & 31;
    const int xbase = bN * 33554432 + ph * 8192 + pw * 16;

    // stage Wq, Wk, Wv (pre-swizzled bf16): linear 32KB copies via cp.async
#pragma unroll
    for (int i = 0; i < 8; i++) {
        int ch = tid + i * 256;          // 2048 16B chunks per weight
        cp16(sb + SMEM_W0 + ch * 16, (const char*)gW[0] + ch * 16);
        cp16(sb + SMEM_W1 + ch * 16, (const char*)gW[1] + ch * 16);
        cp16(sb + SMEM_W2 + ch * 16, (const char*)gW[2] + ch * 16);
    }
    cp_commit();

    // patch load: x -> p^T token-major bf16 swizzled (float4 loads)
#pragma unroll 4
    for (int i = 0; i < 32; i++) {
        int it = tid + i * 256;          // 8192 float4
        int c = it >> 6, q = it & 63;
        int sh = q >> 2, sw4 = (q & 3) << 2;
        float4 v4 = *reinterpret_cast<const float4*>(
            x + xbase + c * 262144 + sh * 512 + sw4);
        int l = sh * 16 + sw4;
        float vv[4] = {v4.x, v4.y, v4.z, v4.w};
#pragma unroll
        for (int j = 0; j < 4; j++) {
            int row = l + j;
            *reinterpret_cast<uint16_t*>(smem + SMEM_P + (uint32_t)row * 256u +
                (uint32_t)((((c >> 3) ^ (row & 7)) << 4) + (c & 7) * 2)) = bf16b(vv[j]);
        }
    }
    cp_wait_all();
    __syncthreads();

    const int g  = lane >> 2;
    const int c4 = (lane & 3) << 1;

    // ---- Q projection -> registers (C-frag -> A-frag identity), 32 rows ----
    uint32_t qa[2][8][4];
    {
        float acc[16][2][4];
#pragma unroll
        for (int nt = 0; nt < 16; nt++)
#pragma unroll
            for (int m = 0; m < 2; m++)
#pragma unroll
                for (int j = 0; j < 4; j++) acc[nt][m][j] = 0.f;
#pragma unroll
        for (int kt = 0; kt < 8; kt++) {
            uint32_t a0[4], a1[4];
            ldsm_x4(mrow(sb + SMEM_P, tm +      (lane & 15), kt * 2 + (lane >> 4)), a0);
            ldsm_x4(mrow(sb + SMEM_P, tm + 16 + (lane & 15), kt * 2 + (lane >> 4)), a1);
#pragma unroll
            for (int np = 0; np < 8; np++) {
                uint32_t wb[4];
                ldsm_x4(mrow(sb + SMEM_W0, np * 16 + (lane & 15),
                             kt * 2 + (lane >> 4)), wb);
                mma16816(acc[2*np][0],   a0, wb[0], wb[2]);
                mma16816(acc[2*np+1][0], a0, wb[1], wb[3]);
                mma16816(acc[2*np][1],   a1, wb[0], wb[2]);
                mma16816(acc[2*np+1][1], a1, wb[1], wb[3]);
            }
        }
#pragma unroll
        for (int kt = 0; kt < 8; kt++) {
            float blo0 = __ldg(bq + 2 * kt * 8 + c4);
            float bhi0 = __ldg(bq + 2 * kt * 8 + c4 + 1);
            float blo1 = __ldg(bq + (2 * kt + 1) * 8 + c4);
            float bhi1 = __ldg(bq + (2 * kt + 1) * 8 + c4 + 1);
#pragma unroll
            for (int m = 0; m < 2; m++) {
                qa[m][kt][0] = pack2bf(acc[2*kt][m][0]   + blo0, acc[2*kt][m][1]   + bhi0);
                qa[m][kt][1] = pack2bf(acc[2*kt][m][2]   + blo0, acc[2*kt][m][3]   + bhi0);
                qa[m][kt][2] = pack2bf(acc[2*kt+1][m][0] + blo1, acc[2*kt+1][m][1] + bhi1);
                qa[m][kt][3] = pack2bf(acc[2*kt+1][m][2] + blo1, acc[2*kt+1][m][3] + bhi1);
            }
        }
    }

    // ---- K projection -> SMEM_K; V projection in-place over P (row-local) --
    proj_store(smem, sb, SMEM_W1, SMEM_K, bk, tm, lane);
    proj_store(smem, sb, SMEM_W2, SMEM_P, bv, tm, lane);
    __syncthreads();

    // stage Wo into W1 (Wk fully consumed above)
#pragma unroll
    for (int i = 0; i < 8; i++) {
        int ch = tid + i * 256;
        cp16(sb + SMEM_W1 + ch * 16, (const char*)gW[3] + ch * 16);
    }
    cp_commit();

    // ---- attention: Y = softmax(Q K^T / tau) V  (no-max exp: logits tiny) --
    float yacc[2][16][4];
#pragma unroll
    for (int m = 0; m < 2; m++)
#pragma unroll
        for (int nt = 0; nt < 16; nt++)
#pragma unroll
            for (int j = 0; j < 4; j++) yacc[m][nt][j] = 0.f;
    float rs[2][2] = {{0.f, 0.f}, {0.f, 0.f}};

#pragma unroll 1
    for (int kc = 0; kc < 16; kc++) {
        const int k0 = kc * 16;
        float s[2][2][4];
#pragma unroll
        for (int m = 0; m < 2; m++)
#pragma unroll
            for (int n = 0; n < 2; n++)
#pragma unroll
                for (int j = 0; j < 4; j++) s[m][n][j] = 0.f;
#pragma unroll
        for (int kt = 0; kt < 8; kt++) {
            uint32_t kb[4];  // [0]=n0-7/k-lo [1]=n8-15/k-lo [2]=n0-7/k-hi [3]=n8-15/k-hi
            ldsm_x4(mrow(sb + SMEM_K, k0 + (lane & 15), kt * 2 + (lane >> 4)), kb);
            mma16816(s[0][0], qa[0][kt], kb[0], kb[2]);
            mma16816(s[0][1], qa[0][kt], kb[1], kb[3]);
            mma16816(s[1][0], qa[1][kt], kb[0], kb[2]);
            mma16816(s[1][1], qa[1][kt], kb[1], kb[3]);
        }
        uint32_t pa[2][4];
#pragma unroll
        for (int m = 0; m < 2; m++) {
            float e0 = __expf(s[m][0][0] * INV_TEMP), e1 = __expf(s[m][0][1] * INV_TEMP);
            float e2 = __expf(s[m][0][2] * INV_TEMP), e3 = __expf(s[m][0][3] * INV_TEMP);
            float f0 = __expf(s[m][1][0] * INV_TEMP), f1 = __expf(s[m][1][1] * INV_TEMP);
            float f2 = __expf(s[m][1][2] * INV_TEMP), f3 = __expf(s[m][1][3] * INV_TEMP);
            pa[m][0] = pack2bf(e0, e1); pa[m][1] = pack2bf(e2, e3);
            pa[m][2] = pack2bf(f0, f1); pa[m][3] = pack2bf(f2, f3);
            rs[m][0] += e0 + e1 + f0 + f1;
            rs[m][1] += e2 + e3 + f2 + f3;
        }
#pragma unroll
        for (int np = 0; np < 8; np++) {
            uint32_t vb[4];  // trans: [0]=b0 nt-lo [1]=b1 nt-lo [2]=b0 nt-hi [3]=b1 nt-hi
            ldsm_x4t(mrow(sb + SMEM_P, k0 + (lane & 15), np * 2 + (lane >> 4)), vb);
            mma16816(yacc[0][2*np],   pa[0], vb[0], vb[1]);
            mma16816(yacc[0][2*np+1], pa[0], vb[2], vb[3]);
            mma16816(yacc[1][2*np],   pa[1], vb[0], vb[1]);
            mma16816(yacc[1][2*np+1], pa[1], vb[2], vb[3]);
        }
    }
#pragma unroll
    for (int m = 0; m < 2; m++)
#pragma unroll
        for (int h = 0; h < 2; h++) {
            float v = rs[m][h];
            v += __shfl_xor_sync(0xffffffffu, v, 1);
            v += __shfl_xor_sync(0xffffffffu, v, 2);
            rs[m][h] = 1.f / v;
        }

    // normalize -> bf16 A frags
    uint32_t ya[2][8][4];
#pragma unroll
    for (int m = 0; m < 2; m++) {
        const float r0 = rs[m][0], r1 = rs[m][1];
#pragma unroll
        for (int kt = 0; kt < 8; kt++) {
            ya[m][kt][0] = pack2bf(yacc[m][2*kt][0]   * r0, yacc[m][2*kt][1]   * r0);
            ya[m][kt][1] = pack2bf(yacc[m][2*kt][2]   * r1, yacc[m][2*kt][3]   * r1);
            ya[m][kt][2] = pack2bf(yacc[m][2*kt+1][0] * r0, yacc[m][2*kt+1][1] * r0);
            ya[m][kt][3] = pack2bf(yacc[m][2*kt+1][2] * r1, yacc[m][2*kt+1][3] * r1);
        }
    }
    cp_wait_all();       // Wo staged
    __syncthreads();     // all K/V reads done; Z may overlay P/K/W0

    // ---- O-projection: Z = Y @ Wo^T, fp32 staged in SMEM (stride 260) ----
    float* zsf = reinterpret_cast<float*>(smem + SMEM_Z);
#pragma unroll 1
    for (int np = 0; np < 8; np++) {
        float z[2][2][4];
#pragma unroll
        for (int m = 0; m < 2; m++)
#pragma unroll
            for (int n = 0; n < 2; n++)
#pragma unroll
                for (int j = 0; j < 4; j++) z[m][n][j] = 0.f;
#pragma unroll
        for (int kt = 0; kt < 8; kt++) {
            uint32_t wb[4];
            ldsm_x4(mrow(sb + SMEM_W1, np * 16 + (lane & 15),
                         kt * 2 + (lane >> 4)), wb);
            mma16816(z[0][0], ya[0][kt], wb[0], wb[2]);
            mma16816(z[0][1], ya[0][kt], wb[1], wb[3]);
            mma16816(z[1][0], ya[1][kt], wb[0], wb[2]);
            mma16816(z[1][1], ya[1][kt], wb[1], wb[3]);
        }
#pragma unroll
        for (int n = 0; n < 2; n++) {
            int c = (2 * np + n) * 8 + c4;
#pragma unroll
            for (int m = 0; m < 2; m++) {
                int r = tm + m * 16 + g;
                zsf[c * 260 + r]           = z[m][n][0];
                zsf[(c + 1) * 260 + r]     = z[m][n][1];
                zsf[c * 260 + r + 8]       = z[m][n][2];
                zsf[(c + 1) * 260 + r + 8] = z[m][n][3];
            }
        }
    }
    __syncthreads();

    // ---- epilogue: out = x + z + bo (coalesced float4, exact residual) ----
#pragma unroll 4
    for (int i = 0; i < 32; i++) {
        int it = tid + i * 256;
        int c = it >> 6, q = it & 63;
        int sh = q >> 2, sw4 = (q & 3) << 2;
        int l = sh * 16 + sw4;
        int ga = xbase + c * 262144 + sh * 512 + sw4;
        float4 xv = *reinterpret_cast<const float4*>(x + ga);
        float4 zv = *reinterpret_cast<const float4*>(zsf + c * 260 + l);
        float bc = __ldg(bo + c);
        float4 ov;
        ov.x = xv.x + zv.x + bc; ov.y = xv.y + zv.y + bc;
        ov.z = xv.z + zv.z + bc; ov.w = xv.w + zv.w + bc;
        *reinterpret_cast<float4*>(out + ga) = ov;
    }
}

extern "C" void kernel_launch(void* const* d_in, const int* in_sizes, int n_in,
                              void* d_out, int out_size) {
    const float* x  = (const float*)d_in[0];
    const float* Wq = (const float*)d_in[1];
    const float* bq = (const float*)d_in[2];
    const float* Wk = (const float*)d_in[3];
    const float* bk = (const float*)d_in[4];
    const float* Wv = (const float*)d_in[5];
    const float* bv = (const float*)d_in[6];
    const float* Wo = (const float*)d_in[7];
    const float* bo = (const float*)d_in[8];
    float* out = (float*)d_out;

    prep_weights<<<32, 256>>>(Wq, Wk, Wv, Wo);

    cudaFuncSetAttribute(PatchAttention_24902220382269_kernel,
                         cudaFuncAttributeMaxDynamicSharedMemorySize, SMEM_TOTAL);
    PatchAttention_24902220382269_kernel<<<2048, 256, SMEM_TOTAL>>>(
        x, bq, bk, bv, bo, out);
}

// round 14
// speedup vs baseline: 1.2206x; 1.2206x over previous
#include <cuda_runtime.h>
#include <cuda_fp16.h>
#include <stdint.h>

// PatchAttention: B=2, C=128, H=W=512, S=16 -> 2048 patches x (L=256, d=128)
// One CTA per patch, 256 threads (8 warps x 32 query rows). Fully fused.
// fp16 operands AND fp16 mma accumulation (half the accum regs of R11 -> no
// spills at 32 rows/warp, half the per-CTA SMEM B-traffic of R8).

#define SMEM_P     0u        // p^T, later V : [256][128] f16 swizzled (64 KB)
#define SMEM_K     65536u    // K            : [256][128] f16 swizzled (64 KB)
#define SMEM_W0    131072u   // Wq stage (32 KB)
#define SMEM_W1    163840u   // Wk stage, later Wo (32 KB)
#define SMEM_W2    196608u   // Wv stage (32 KB)
#define SMEM_Z     0u        // phase-3 Z [128][260] f32 (overlays P,K,W0-head)
#define SMEM_TOTAL 229376u

#define INV_TEMP 0.08838834764831845f  // 1/sqrt(128)

__device__ uint32_t gW[4][8192];  // f16x2-packed, swizzled: Wq, Wk, Wv, Wo

__device__ __forceinline__ uint32_t pack2h(float lo, float hi) {
    uint32_t r;
    asm("cvt.rn.f16x2.f32 %0, %1, %2;" : "=r"(r) : "f"(hi), "f"(lo));
    return r;
}
__device__ __forceinline__ float2 up2h(uint32_t u) {
    __half2 h = *reinterpret_cast<__half2*>(&u);
    return __half22float2(h);
}
__device__ __forceinline__ uint16_t h16(float v) {
    uint16_t r;
    asm("cvt.rn.f16.f32 %0, %1;" : "=h"(r) : "f"(v));
    return r;
}
// swizzled address in a matrix of 256B rows (128 f16); 16B chunk ^= row&7
__device__ __forceinline__ uint32_t mrow(uint32_t base, int row, int chunk) {
    return base + (uint32_t)row * 256u + (uint32_t)(((chunk ^ (row & 7)) << 4));
}
__device__ __forceinline__ void ldsm_x4(uint32_t a, uint32_t r[4]) {
    asm volatile("ldmatrix.sync.aligned.m8n8.x4.shared.b16 {%0,%1,%2,%3}, [%4];"
                 : "=r"(r[0]), "=r"(r[1]), "=r"(r[2]), "=r"(r[3]) : "r"(a));
}
__device__ __forceinline__ void ldsm_x4t(uint32_t a, uint32_t r[4]) {
    asm volatile("ldmatrix.sync.aligned.m8n8.x4.trans.shared.b16 {%0,%1,%2,%3}, [%4];"
                 : "=r"(r[0]), "=r"(r[1]), "=r"(r[2]), "=r"(r[3]) : "r"(a));
}
// f16 accumulate: D,C = 2 regs (packed pairs, same positions as f32 c0..c3)
__device__ __forceinline__ void mma_h(uint32_t c[2], const uint32_t a[4],
                                      uint32_t b0, uint32_t b1) {
    asm volatile(
        "mma.sync.aligned.m16n8k16.row.col.f16.f16.f16.f16 "
        "{%0,%1},{%2,%3,%4,%5},{%6,%7},{%0,%1};"
        : "+r"(c[0]), "+r"(c[1])
        : "r"(a[0]), "r"(a[1]), "r"(a[2]), "r"(a[3]), "r"(b0), "r"(b1));
}
__device__ __forceinline__ void cp16(uint32_t s, const void* g) {
    asm volatile("cp.async.ca.shared.global [%0], [%1], 16;" :: "r"(s), "l"(g));
}
__device__ __forceinline__ void cp_commit() { asm volatile("cp.async.commit_group;"); }
__device__ __forceinline__ void cp_wait_all() { asm volatile("cp.async.wait_group 0;"); }

// ---- prep: fp32 weights -> f16x2 packed, swizzled, into gW -----------------
__global__ void prep_weights(const float* __restrict__ Wq,
                             const float* __restrict__ Wk,
                             const float* __restrict__ Wv,
                             const float* __restrict__ Wo) {
    const float* Ws[4] = {Wq, Wk, Wv, Wo};
    int t = blockIdx.x * 256 + threadIdx.x;  // 8192 threads
#pragma unroll
    for (int i = 0; i < 4; i++) {
        int idx = t + i * 8192;              // 32768 total u32 slots
        int w = idx >> 13, rem = idx & 8191;
        int d = rem >> 6, j = rem & 63;      // j = column-pair index
        float2 v = *reinterpret_cast<const float2*>(Ws[w] + d * 128 + 2 * j);
        gW[w][d * 64 + (((j >> 2) ^ (d & 7)) << 2) + (j & 3)] = pack2h(v.x, v.y);
    }
}

// projection: dst(own 32 rows) = P(own rows) @ W^T + bias, f16 -> SMEM
__device__ __forceinline__ void proj_store(char* smem, uint32_t sb,
                                           uint32_t wOff, uint32_t dOff,
                                           const float* __restrict__ bias,
                                           int tm, int lane) {
    uint32_t acc[16][2][2];
#pragma unroll
    for (int nt = 0; nt < 16; nt++)
#pragma unroll
        for (int m = 0; m < 2; m++) { acc[nt][m][0] = 0u; acc[nt][m][1] = 0u; }
#pragma unroll
    for (int kt = 0; kt < 8; kt++) {
        uint32_t a0[4], a1[4];
        ldsm_x4(mrow(sb + SMEM_P, tm +      (lane & 15), kt * 2 + (lane >> 4)), a0);
        ldsm_x4(mrow(sb + SMEM_P, tm + 16 + (lane & 15), kt * 2 + (lane >> 4)), a1);
#pragma unroll
        for (int np = 0; np < 8; np++) {
            uint32_t wb[4];
            ldsm_x4(mrow(sb + wOff, np * 16 + (lane & 15), kt * 2 + (lane >> 4)), wb);
            mma_h(acc[2*np][0],   a0, wb[0], wb[2]);
            mma_h(acc[2*np+1][0], a0, wb[1], wb[3]);
            mma_h(acc[2*np][1],   a1, wb[0], wb[2]);
            mma_h(acc[2*np+1][1], a1, wb[1], wb[3]);
        }
    }
    const int g  = lane >> 2;
    const int c4 = (lane & 3) << 1;
#pragma unroll
    for (int nt = 0; nt < 16; nt++) {
        float blo = __ldg(bias + nt * 8 + c4);
        float bhi = __ldg(bias + nt * 8 + c4 + 1);
#pragma unroll
        for (int m = 0; m < 2; m++) {
            int r = tm + m * 16 + g;
            float2 lo = up2h(acc[nt][m][0]);   // (row r,   cols c4, c4+1)
            float2 hi = up2h(acc[nt][m][1]);   // (row r+8, cols c4, c4+1)
            uint32_t cb = (uint32_t)(((nt ^ (r & 7)) << 4) + c4 * 2);
            *reinterpret_cast<uint32_t*>(smem + dOff + (uint32_t)r * 256u + cb) =
                pack2h(lo.x + blo, lo.y + bhi);
            *reinterpret_cast<uint32_t*>(smem + dOff + (uint32_t)(r + 8) * 256u + cb) =
                pack2h(hi.x + blo, hi.y + bhi);
        }
    }
}

__global__ void __launch_bounds__(256, 1)
PatchAttention_24902220382269_kernel(
    const float* __restrict__ x,
    const float* __restrict__ bq, const float* __restrict__ bk,
    const float* __restrict__ bv, const float* __restrict__ bo,
    float* __restrict__ out)
{
    extern __shared__ char smem[];
    const uint32_t sb = (uint32_t)__cvta_generic_to_shared(smem);
    const int tid  = threadIdx.x;
    const int lane = tid & 31;
    const int warp = tid >> 5;
    const int tm   = warp * 32;          // 32 query rows per warp

    const int pid   = blockIdx.x;
    const int bN    = pid >> 10;
    const int ph    = (pid >> 5) & 31;
    const int pw    = pid & 31;
    const int xbase = bN * 33554432 + ph * 8192 + pw * 16;

    // stage Wq, Wk, Wv (pre-swizzled f16)
#pragma unroll
    for (int i = 0; i < 8; i++) {
        int ch = tid + i * 256;
        cp16(sb + SMEM_W0 + ch * 16, (const char*)gW[0] + ch * 16);
        cp16(sb + SMEM_W1 + ch * 16, (const char*)gW[1] + ch * 16);
        cp16(sb + SMEM_W2 + ch * 16, (const char*)gW[2] + ch * 16);
    }
    cp_commit();

    // patch load: x -> p^T token-major f16 swizzled
#pragma unroll 4
    for (int i = 0; i < 32; i++) {
        int it = tid + i * 256;
        int c = it >> 6, q = it & 63;
        int sh = q >> 2, sw4 = (q & 3) << 2;
        float4 v4 = *reinterpret_cast<const float4*>(
            x + xbase + c * 262144 + sh * 512 + sw4);
        int l = sh * 16 + sw4;
        float vv[4] = {v4.x, v4.y, v4.z, v4.w};
#pragma unroll
        for (int j = 0; j < 4; j++) {
            int row = l + j;
            *reinterpret_cast<uint16_t*>(smem + SMEM_P + (uint32_t)row * 256u +
                (uint32_t)((((c >> 3) ^ (row & 7)) << 4) + (c & 7) * 2)) = h16(vv[j]);
        }
    }
    cp_wait_all();
    __syncthreads();

    const int g  = lane >> 2;
    const int c4 = (lane & 3) << 1;

    // ---- Q projection -> registers (f16 C-frag == A-frag packing) ----
    uint32_t qa[2][8][4];
    {
        uint32_t acc[16][2][2];
#pragma unroll
        for (int nt = 0; nt < 16; nt++)
#pragma unroll
            for (int m = 0; m < 2; m++) { acc[nt][m][0] = 0u; acc[nt][m][1] = 0u; }
#pragma unroll
        for (int kt = 0; kt < 8; kt++) {
            uint32_t a0[4], a1[4];
            ldsm_x4(mrow(sb + SMEM_P, tm +      (lane & 15), kt * 2 + (lane >> 4)), a0);
            ldsm_x4(mrow(sb + SMEM_P, tm + 16 + (lane & 15), kt * 2 + (lane >> 4)), a1);
#pragma unroll
            for (int np = 0; np < 8; np++) {
                uint32_t wb[4];
                ldsm_x4(mrow(sb + SMEM_W0, np * 16 + (lane & 15),
                             kt * 2 + (lane >> 4)), wb);
                mma_h(acc[2*np][0],   a0, wb[0], wb[2]);
                mma_h(acc[2*np+1][0], a0, wb[1], wb[3]);
                mma_h(acc[2*np][1],   a1, wb[0], wb[2]);
                mma_h(acc[2*np+1][1], a1, wb[1], wb[3]);
            }
        }
#pragma unroll
        for (int kt = 0; kt < 8; kt++) {
            float blo0 = __ldg(bq + 2 * kt * 8 + c4);
            float bhi0 = __ldg(bq + 2 * kt * 8 + c4 + 1);
            float blo1 = __ldg(bq + (2 * kt + 1) * 8 + c4);
            float bhi1 = __ldg(bq + (2 * kt + 1) * 8 + c4 + 1);
#pragma unroll
            for (int m = 0; m < 2; m++) {
                float2 v0 = up2h(acc[2*kt][m][0]);
                float2 v1 = up2h(acc[2*kt][m][1]);
                float2 v2 = up2h(acc[2*kt+1][m][0]);
                float2 v3 = up2h(acc[2*kt+1][m][1]);
                qa[m][kt][0] = pack2h(v0.x + blo0, v0.y + bhi0);
                qa[m][kt][1] = pack2h(v1.x + blo0, v1.y + bhi0);
                qa[m][kt][2] = pack2h(v2.x + blo1, v2.y + bhi1);
                qa[m][kt][3] = pack2h(v3.x + blo1, v3.y + bhi1);
            }
        }
    }

    // ---- K projection -> SMEM_K; V projection in-place over P (row-local) --
    proj_store(smem, sb, SMEM_W1, SMEM_K, bk, tm, lane);
    proj_store(smem, sb, SMEM_W2, SMEM_P, bv, tm, lane);
    __syncthreads();

    // stage Wo into W1 (Wk fully consumed above)
#pragma unroll
    for (int i = 0; i < 8; i++) {
        int ch = tid + i * 256;
        cp16(sb + SMEM_W1 + ch * 16, (const char*)gW[3] + ch * 16);
    }
    cp_commit();

    // ---- attention: Y = softmax(Q K^T / tau) V  (no-max exp: logits tiny) --
    uint32_t yacc[2][16][2];
#pragma unroll
    for (int m = 0; m < 2; m++)
#pragma unroll
        for (int nt = 0; nt < 16; nt++) { yacc[m][nt][0] = 0u; yacc[m][nt][1] = 0u; }
    float rs[2][2] = {{0.f, 0.f}, {0.f, 0.f}};

#pragma unroll 1
    for (int kc = 0; kc < 16; kc++) {
        const int k0 = kc * 16;
        uint32_t s[2][2][2];
#pragma unroll
        for (int m = 0; m < 2; m++)
#pragma unroll
            for (int n = 0; n < 2; n++) { s[m][n][0] = 0u; s[m][n][1] = 0u; }
#pragma unroll
        for (int kt = 0; kt < 8; kt++) {
            uint32_t kb[4];
            ldsm_x4(mrow(sb + SMEM_K, k0 + (lane & 15), kt * 2 + (lane >> 4)), kb);
            mma_h(s[0][0], qa[0][kt], kb[0], kb[2]);
            mma_h(s[0][1], qa[0][kt], kb[1], kb[3]);
            mma_h(s[1][0], qa[1][kt], kb[0], kb[2]);
            mma_h(s[1][1], qa[1][kt], kb[1], kb[3]);
        }
        uint32_t pa[2][4];
#pragma unroll
        for (int m = 0; m < 2; m++) {
            float2 e01 = up2h(s[m][0][0]);     // (row g,   keys 2t,2t+1)
            float2 e23 = up2h(s[m][0][1]);     // (row g+8)
            float2 f01 = up2h(s[m][1][0]);
            float2 f23 = up2h(s[m][1][1]);
            float e0 = __expf(e01.x * INV_TEMP), e1 = __expf(e01.y * INV_TEMP);
            float e2 = __expf(e23.x * INV_TEMP), e3 = __expf(e23.y * INV_TEMP);
            float f0 = __expf(f01.x * INV_TEMP), f1 = __expf(f01.y * INV_TEMP);
            float f2 = __expf(f23.x * INV_TEMP), f3 = __expf(f23.y * INV_TEMP);
            pa[m][0] = pack2h(e0, e1); pa[m][1] = pack2h(e2, e3);
            pa[m][2] = pack2h(f0, f1); pa[m][3] = pack2h(f2, f3);
            rs[m][0] += e0 + e1 + f0 + f1;     // row g
            rs[m][1] += e2 + e3 + f2 + f3;     // row g+8
        }
#pragma unroll
        for (int np = 0; np < 8; np++) {
            uint32_t vb[4];
            ldsm_x4t(mrow(sb + SMEM_P, k0 + (lane & 15), np * 2 + (lane >> 4)), vb);
            mma_h(yacc[0][2*np],   pa[0], vb[0], vb[1]);
            mma_h(yacc[0][2*np+1], pa[0], vb[2], vb[3]);
            mma_h(yacc[1][2*np],   pa[1], vb[0], vb[1]);
            mma_h(yacc[1][2*np+1], pa[1], vb[2], vb[3]);
        }
    }
#pragma unroll
    for (int m = 0; m < 2; m++)
#pragma unroll
        for (int h = 0; h < 2; h++) {
            float v = rs[m][h];
            v += __shfl_xor_sync(0xffffffffu, v, 1);
            v += __shfl_xor_sync(0xffffffffu, v, 2);
            rs[m][h] = 1.f / v;
        }

    // normalize -> f16 A frags
    uint32_t ya[2][8][4];
#pragma unroll
    for (int m = 0; m < 2; m++) {
        const float r0 = rs[m][0], r1 = rs[m][1];
#pragma unroll
        for (int kt = 0; kt < 8; kt++) {
            float2 v0 = up2h(yacc[m][2*kt][0]);
            float2 v1 = up2h(yacc[m][2*kt][1]);
            float2 v2 = up2h(yacc[m][2*kt+1][0]);
            float2 v3 = up2h(yacc[m][2*kt+1][1]);
            ya[m][kt][0] = pack2h(v0.x * r0, v0.y * r0);
            ya[m][kt][1] = pack2h(v1.x * r1, v1.y * r1);
            ya[m][kt][2] = pack2h(v2.x * r0, v2.y * r0);
            ya[m][kt][3] = pack2h(v3.x * r1, v3.y * r1);
        }
    }
    cp_wait_all();       // Wo staged
    __syncthreads();     // all K/V reads done; Z may overlay P/K/W0

    // ---- O-projection: Z = Y @ Wo^T, fp32 staged in SMEM (stride 260) ----
    float* zsf = reinterpret_cast<float*>(smem + SMEM_Z);
#pragma unroll 1
    for (int np = 0; np < 8; np++) {
        uint32_t z[2][2][2];
#pragma unroll
        for (int m = 0; m < 2; m++)
#pragma unroll
            for (int n = 0; n < 2; n++) { z[m][n][0] = 0u; z[m][n][1] = 0u; }
#pragma unroll
        for (int kt = 0; kt < 8; kt++) {
            uint32_t wb[4];
            ldsm_x4(mrow(sb + SMEM_W1, np * 16 + (lane & 15),
                         kt * 2 + (lane >> 4)), wb);
            mma_h(z[0][0], ya[0][kt], wb[0], wb[2]);
            mma_h(z[0][1], ya[0][kt], wb[1], wb[3]);
            mma_h(z[1][0], ya[1][kt], wb[0], wb[2]);
            mma_h(z[1][1], ya[1][kt], wb[1], wb[3]);
        }
#pragma unroll
        for (int n = 0; n < 2; n++) {
            int c = (2 * np + n) * 8 + c4;
#pragma unroll
            for (int m = 0; m < 2; m++) {
                int r = tm + m * 16 + g;
                float2 lo = up2h(z[m][n][0]);  // rows r:   cols c, c+1
                float2 hi = up2h(z[m][n][1]);  // rows r+8
                zsf[c * 260 + r]           = lo.x;
                zsf[(c + 1) * 260 + r]     = lo.y;
                zsf[c * 260 + r + 8]       = hi.x;
                zsf[(c + 1) * 260 + r + 8] = hi.y;
            }
        }
    }
    __syncthreads();

    // ---- epilogue: out = x + z + bo (coalesced float4, exact residual) ----
#pragma unroll 4
    for (int i = 0; i < 32; i++) {
        int it = tid + i * 256;
        int c = it >> 6, q = it & 63;
        int sh = q >> 2, sw4 = (q & 3) << 2;
        int l = sh * 16 + sw4;
        int ga = xbase + c * 262144 + sh * 512 + sw4;
        float4 xv = *reinterpret_cast<const float4*>(x + ga);
        float4 zv = *reinterpret_cast<const float4*>(zsf + c * 260 + l);
        float bc = __ldg(bo + c);
        float4 ov;
        ov.x = xv.x + zv.x + bc; ov.y = xv.y + zv.y + bc;
        ov.z = xv.z + zv.z + bc; ov.w = xv.w + zv.w + bc;
        *reinterpret_cast<float4*>(out + ga) = ov;
    }
}

extern "C" void kernel_launch(void* const* d_in, const int* in_sizes, int n_in,
                              void* d_out, int out_size) {
    const float* x  = (const float*)d_in[0];
    const float* Wq = (const float*)d_in[1];
    const float* bq = (const float*)d_in[2];
    const float* Wk = (const float*)d_in[3];
    const float* bk = (const float*)d_in[4];
    const float* Wv = (const float*)d_in[5];
    const float* bv = (const float*)d_in[6];
    const float* Wo = (const float*)d_in[7];
    const float* bo = (const float*)d_in[8];
    float* out = (float*)d_out;

    prep_weights<<<32, 256>>>(Wq, Wk, Wv, Wo);

    cudaFuncSetAttribute(PatchAttention_24902220382269_kernel,
                         cudaFuncAttributeMaxDynamicSharedMemorySize, SMEM_TOTAL);
    PatchAttention_24902220382269_kernel<<<2048, 256, SMEM_TOTAL>>>(
        x, bq, bk, bv, bo, out);
}

// round 15
// speedup vs baseline: 1.2570x; 1.0299x over previous
#include <cuda_runtime.h>
#include <cuda_fp16.h>
#include <stdint.h>

// PatchAttention: B=2, C=128, H=W=512, S=16 -> 2048 patches x (L=256, d=128)
// One CTA per patch, 256 threads (8 warps x 32 query rows). Fully fused, f16
// mma accumulation. R15: pipelined attention (S(kc+1) overlaps PV(kc)),
// log2e/tau folded into Wq/bq at prep, ex2.approx.f16x2 softmax, f16x2 bias
// adds (HADD2) in all projection epilogues.

#define SMEM_P     0u        // p^T, later V : [256][128] f16 swizzled (64 KB)
#define SMEM_K     65536u    // K            : [256][128] f16 swizzled (64 KB)
#define SMEM_W0    131072u   // Wq stage (32 KB)
#define SMEM_W1    163840u   // Wk stage, later Wo (32 KB)
#define SMEM_W2    196608u   // Wv stage (32 KB)
#define SMEM_Z     0u        // phase-3 Z [128][260] f32 (overlays P,K,W0-head)
#define SMEM_TOTAL 229376u

#define QSCALE ((float)(1.4426950408889634 / 11.313708498984761))  // log2e/sqrt(128)

__device__ uint32_t gW[4][8192];  // f16x2-packed, swizzled: Wq*QSCALE, Wk, Wv, Wo
__device__ uint32_t gB[3][64];    // f16x2 column-pair biases: bq*QSCALE, bk, bv

__device__ __forceinline__ uint32_t pack2h(float lo, float hi) {
    uint32_t r;
    asm("cvt.rn.f16x2.f32 %0, %1, %2;" : "=r"(r) : "f"(hi), "f"(lo));
    return r;
}
__device__ __forceinline__ float2 up2h(uint32_t u) {
    __half2 h = *reinterpret_cast<__half2*>(&u);
    return __half22float2(h);
}
__device__ __forceinline__ uint16_t h16(float v) {
    uint16_t r;
    asm("cvt.rn.f16.f32 %0, %1;" : "=h"(r) : "f"(v));
    return r;
}
__device__ __forceinline__ uint32_t hadd2u(uint32_t a, uint32_t b) {
    uint32_t d; asm("add.rn.f16x2 %0, %1, %2;" : "=r"(d) : "r"(a), "r"(b)); return d;
}
__device__ __forceinline__ uint32_t hmul2u(uint32_t a, uint32_t b) {
    uint32_t d; asm("mul.rn.f16x2 %0, %1, %2;" : "=r"(d) : "r"(a), "r"(b)); return d;
}
__device__ __forceinline__ uint32_t ex2u(uint32_t a) {
    uint32_t d; asm("ex2.approx.f16x2 %0, %1;" : "=r"(d) : "r"(a)); return d;
}
// swizzled address in a matrix of 256B rows (128 f16); 16B chunk ^= row&7
__device__ __forceinline__ uint32_t mrow(uint32_t base, int row, int chunk) {
    return base + (uint32_t)row * 256u + (uint32_t)(((chunk ^ (row & 7)) << 4));
}
__device__ __forceinline__ void ldsm_x4(uint32_t a, uint32_t r[4]) {
    asm volatile("ldmatrix.sync.aligned.m8n8.x4.shared.b16 {%0,%1,%2,%3}, [%4];"
                 : "=r"(r[0]), "=r"(r[1]), "=r"(r[2]), "=r"(r[3]) : "r"(a));
}
__device__ __forceinline__ void ldsm_x4t(uint32_t a, uint32_t r[4]) {
    asm volatile("ldmatrix.sync.aligned.m8n8.x4.trans.shared.b16 {%0,%1,%2,%3}, [%4];"
                 : "=r"(r[0]), "=r"(r[1]), "=r"(r[2]), "=r"(r[3]) : "r"(a));
}
__device__ __forceinline__ void mma_h(uint32_t c[2], const uint32_t a[4],
                                      uint32_t b0, uint32_t b1) {
    asm volatile(
        "mma.sync.aligned.m16n8k16.row.col.f16.f16.f16.f16 "
        "{%0,%1},{%2,%3,%4,%5},{%6,%7},{%0,%1};"
        : "+r"(c[0]), "+r"(c[1])
        : "r"(a[0]), "r"(a[1]), "r"(a[2]), "r"(a[3]), "r"(b0), "r"(b1));
}
__device__ __forceinline__ void cp16(uint32_t s, const void* g) {
    asm volatile("cp.async.ca.shared.global [%0], [%1], 16;" :: "r"(s), "l"(g));
}
__device__ __forceinline__ void cp_commit() { asm volatile("cp.async.commit_group;"); }
__device__ __forceinline__ void cp_wait_all() { asm volatile("cp.async.wait_group 0;"); }

// ---- prep: fp32 weights/biases -> f16x2 packed (Wq,bq pre-scaled) ----------
__global__ void prep_weights(const float* __restrict__ Wq,
                             const float* __restrict__ Wk,
                             const float* __restrict__ Wv,
                             const float* __restrict__ Wo,
                             const float* __restrict__ bq,
                             const float* __restrict__ bk,
                             const float* __restrict__ bv) {
    const float* Ws[4] = {Wq, Wk, Wv, Wo};
    int t = blockIdx.x * 256 + threadIdx.x;  // 8192 threads
#pragma unroll
    for (int i = 0; i < 4; i++) {
        int idx = t + i * 8192;              // 32768 total u32 slots
        int w = idx >> 13, rem = idx & 8191;
        int d = rem >> 6, j = rem & 63;
        float sc = (w == 0) ? QSCALE : 1.f;
        float2 v = *reinterpret_cast<const float2*>(Ws[w] + d * 128 + 2 * j);
        gW[w][d * 64 + (((j >> 2) ^ (d & 7)) << 2) + (j & 3)] =
            pack2h(v.x * sc, v.y * sc);
    }
    if (blockIdx.x == 0 && threadIdx.x < 192) {
        int w = threadIdx.x >> 6, j = threadIdx.x & 63;
        const float* bs[3] = {bq, bk, bv};
        float sc = (w == 0) ? QSCALE : 1.f;
        gB[w][j] = pack2h(bs[w][2*j] * sc, bs[w][2*j+1] * sc);
    }
}

// projection: dst(own 32 rows) = P(own rows) @ W^T + bias2, f16 -> SMEM
__device__ __forceinline__ void proj_store(char* smem, uint32_t sb,
                                           uint32_t wOff, uint32_t dOff,
                                           const uint32_t* __restrict__ b2,
                                           int tm, int lane) {
    uint32_t acc[16][2][2];
#pragma unroll
    for (int nt = 0; nt < 16; nt++)
#pragma unroll
        for (int m = 0; m < 2; m++) { acc[nt][m][0] = 0u; acc[nt][m][1] = 0u; }
#pragma unroll
    for (int kt = 0; kt < 8; kt++) {
        uint32_t a0[4], a1[4];
        ldsm_x4(mrow(sb + SMEM_P, tm +      (lane & 15), kt * 2 + (lane >> 4)), a0);
        ldsm_x4(mrow(sb + SMEM_P, tm + 16 + (lane & 15), kt * 2 + (lane >> 4)), a1);
#pragma unroll
        for (int np = 0; np < 8; np++) {
            uint32_t wb[4];
            ldsm_x4(mrow(sb + wOff, np * 16 + (lane & 15), kt * 2 + (lane >> 4)), wb);
            mma_h(acc[2*np][0],   a0, wb[0], wb[2]);
            mma_h(acc[2*np+1][0], a0, wb[1], wb[3]);
            mma_h(acc[2*np][1],   a1, wb[0], wb[2]);
            mma_h(acc[2*np+1][1], a1, wb[1], wb[3]);
        }
    }
    const int g  = lane >> 2;
    const int c4 = (lane & 3) << 1;
#pragma unroll
    for (int nt = 0; nt < 16; nt++) {
        uint32_t bias2 = __ldg(b2 + nt * 4 + (lane & 3));
#pragma unroll
        for (int m = 0; m < 2; m++) {
            int r = tm + m * 16 + g;
            uint32_t cb = (uint32_t)(((nt ^ (r & 7)) << 4) + c4 * 2);
            *reinterpret_cast<uint32_t*>(smem + dOff + (uint32_t)r * 256u + cb) =
                hadd2u(acc[nt][m][0], bias2);
            *reinterpret_cast<uint32_t*>(smem + dOff + (uint32_t)(r + 8) * 256u + cb) =
                hadd2u(acc[nt][m][1], bias2);
        }
    }
}

__global__ void __launch_bounds__(256, 1)
PatchAttention_24902220382269_kernel(
    const float* __restrict__ x,
    const float* __restrict__ bo,
    float* __restrict__ out)
{
    extern __shared__ char smem[];
    const uint32_t sb = (uint32_t)__cvta_generic_to_shared(smem);
    const int tid  = threadIdx.x;
    const int lane = tid & 31;
    const int warp = tid >> 5;
    const int tm   = warp * 32;          // 32 query rows per warp

    const int pid   = blockIdx.x;
    const int bN    = pid >> 10;
    const int ph    = (pid >> 5) & 31;
    const int pw    = pid & 31;
    const int xbase = bN * 33554432 + ph * 8192 + pw * 16;

    // stage Wq, Wk, Wv (pre-swizzled f16)
#pragma unroll
    for (int i = 0; i < 8; i++) {
        int ch = tid + i * 256;
        cp16(sb + SMEM_W0 + ch * 16, (const char*)gW[0] + ch * 16);
        cp16(sb + SMEM_W1 + ch * 16, (const char*)gW[1] + ch * 16);
        cp16(sb + SMEM_W2 + ch * 16, (const char*)gW[2] + ch * 16);
    }
    cp_commit();

    // patch load: x -> p^T token-major f16 swizzled
#pragma unroll 4
    for (int i = 0; i < 32; i++) {
        int it = tid + i * 256;
        int c = it >> 6, q = it & 63;
        int sh = q >> 2, sw4 = (q & 3) << 2;
        float4 v4 = *reinterpret_cast<const float4*>(
            x + xbase + c * 262144 + sh * 512 + sw4);
        int l = sh * 16 + sw4;
        float vv[4] = {v4.x, v4.y, v4.z, v4.w};
#pragma unroll
        for (int j = 0; j < 4; j++) {
            int row = l + j;
            *reinterpret_cast<uint16_t*>(smem + SMEM_P + (uint32_t)row * 256u +
                (uint32_t)((((c >> 3) ^ (row & 7)) << 4) + (c & 7) * 2)) = h16(vv[j]);
        }
    }
    cp_wait_all();
    __syncthreads();

    const int g  = lane >> 2;

    // ---- Q projection -> registers (f16 C-frag == A-frag packing) ----
    uint32_t qa[2][8][4];
    {
        uint32_t acc[16][2][2];
#pragma unroll
        for (int nt = 0; nt < 16; nt++)
#pragma unroll
            for (int m = 0; m < 2; m++) { acc[nt][m][0] = 0u; acc[nt][m][1] = 0u; }
#pragma unroll
        for (int kt = 0; kt < 8; kt++) {
            uint32_t a0[4], a1[4];
            ldsm_x4(mrow(sb + SMEM_P, tm +      (lane & 15), kt * 2 + (lane >> 4)), a0);
            ldsm_x4(mrow(sb + SMEM_P, tm + 16 + (lane & 15), kt * 2 + (lane >> 4)), a1);
#pragma unroll
            for (int np = 0; np < 8; np++) {
                uint32_t wb[4];
                ldsm_x4(mrow(sb + SMEM_W0, np * 16 + (lane & 15),
                             kt * 2 + (lane >> 4)), wb);
                mma_h(acc[2*np][0],   a0, wb[0], wb[2]);
                mma_h(acc[2*np+1][0], a0, wb[1], wb[3]);
                mma_h(acc[2*np][1],   a1, wb[0], wb[2]);
                mma_h(acc[2*np+1][1], a1, wb[1], wb[3]);
            }
        }
#pragma unroll
        for (int kt = 0; kt < 8; kt++) {
            uint32_t b0 = __ldg(&gB[0][8 * kt +     (lane & 3)]);
            uint32_t b1 = __ldg(&gB[0][8 * kt + 4 + (lane & 3)]);
#pragma unroll
            for (int m = 0; m < 2; m++) {
                qa[m][kt][0] = hadd2u(acc[2*kt][m][0],   b0);
                qa[m][kt][1] = hadd2u(acc[2*kt][m][1],   b0);
                qa[m][kt][2] = hadd2u(acc[2*kt+1][m][0], b1);
                qa[m][kt][3] = hadd2u(acc[2*kt+1][m][1], b1);
            }
        }
    }

    // ---- K projection -> SMEM_K; V projection in-place over P (row-local) --
    proj_store(smem, sb, SMEM_W1, SMEM_K, gB[1], tm, lane);
    proj_store(smem, sb, SMEM_W2, SMEM_P, gB[2], tm, lane);
    __syncthreads();

    // stage Wo into W1 (Wk fully consumed above)
#pragma unroll
    for (int i = 0; i < 8; i++) {
        int ch = tid + i * 256;
        cp16(sb + SMEM_W1 + ch * 16, (const char*)gW[3] + ch * 16);
    }
    cp_commit();

    // ---- attention (pipelined): Y = softmax(Q K^T) V ----
    // Q pre-scaled by log2e/tau -> pa = ex2(S) directly. s flat: [m*4 + n*2 + r]
    uint32_t yacc[2][16][2];
#pragma unroll
    for (int m = 0; m < 2; m++)
#pragma unroll
        for (int nt = 0; nt < 16; nt++) { yacc[m][nt][0] = 0u; yacc[m][nt][1] = 0u; }
    float rs[2][2] = {{0.f, 0.f}, {0.f, 0.f}};

    auto computeS = [&](int k0, uint32_t s[8]) {
#pragma unroll
        for (int i = 0; i < 8; i++) s[i] = 0u;
#pragma unroll
        for (int kt = 0; kt < 8; kt++) {
            uint32_t kb[4];
            ldsm_x4(mrow(sb + SMEM_K, k0 + (lane & 15), kt * 2 + (lane >> 4)), kb);
            mma_h(s + 0, qa[0][kt], kb[0], kb[2]);
            mma_h(s + 2, qa[0][kt], kb[1], kb[3]);
            mma_h(s + 4, qa[1][kt], kb[0], kb[2]);
            mma_h(s + 6, qa[1][kt], kb[1], kb[3]);
        }
    };

    uint32_t scur[8];
    computeS(0, scur);
#pragma unroll 1
    for (int kc = 0; kc < 16; kc++) {
        uint32_t pa[2][4];
#pragma unroll
        for (int m = 0; m < 2; m++) {
            pa[m][0] = ex2u(scur[m*4 + 0]);
            pa[m][1] = ex2u(scur[m*4 + 1]);
            pa[m][2] = ex2u(scur[m*4 + 2]);
            pa[m][3] = ex2u(scur[m*4 + 3]);
            float2 t0 = up2h(hadd2u(pa[m][0], pa[m][2]));  // row g
            float2 t1 = up2h(hadd2u(pa[m][1], pa[m][3]));  // row g+8
            rs[m][0] += t0.x + t0.y;
            rs[m][1] += t1.x + t1.y;
        }
        uint32_t snxt[8];
        if (kc < 15) computeS((kc + 1) * 16, snxt);
#pragma unroll
        for (int np = 0; np < 8; np++) {
            uint32_t vb[4];
            ldsm_x4t(mrow(sb + SMEM_P, kc * 16 + (lane & 15), np * 2 + (lane >> 4)), vb);
            mma_h(yacc[0][2*np],   pa[0], vb[0], vb[1]);
            mma_h(yacc[0][2*np+1], pa[0], vb[2], vb[3]);
            mma_h(yacc[1][2*np],   pa[1], vb[0], vb[1]);
            mma_h(yacc[1][2*np+1], pa[1], vb[2], vb[3]);
        }
        if (kc < 15) {
#pragma unroll
            for (int i = 0; i < 8; i++) scur[i] = snxt[i];
        }
    }
#pragma unroll
    for (int m = 0; m < 2; m++)
#pragma unroll
        for (int h = 0; h < 2; h++) {
            float v = rs[m][h];
            v += __shfl_xor_sync(0xffffffffu, v, 1);
            v += __shfl_xor_sync(0xffffffffu, v, 2);
            rs[m][h] = 1.f / v;
        }

    // normalize -> f16 A frags (HMUL2 on packed pairs)
    uint32_t ya[2][8][4];
#pragma unroll
    for (int m = 0; m < 2; m++) {
        uint32_t rr0 = pack2h(rs[m][0], rs[m][0]);
        uint32_t rr1 = pack2h(rs[m][1], rs[m][1]);
#pragma unroll
        for (int kt = 0; kt < 8; kt++) {
            ya[m][kt][0] = hmul2u(yacc[m][2*kt][0],   rr0);
            ya[m][kt][1] = hmul2u(yacc[m][2*kt][1],   rr1);
            ya[m][kt][2] = hmul2u(yacc[m][2*kt+1][0], rr0);
            ya[m][kt][3] = hmul2u(yacc[m][2*kt+1][1], rr1);
        }
    }
    cp_wait_all();       // Wo staged
    __syncthreads();     // all K/V reads done; Z may overlay P/K/W0

    // ---- O-projection: Z = Y @ Wo^T, fp32 staged in SMEM (stride 260) ----
    float* zsf = reinterpret_cast<float*>(smem + SMEM_Z);
    const int c4 = (lane & 3) << 1;
#pragma unroll 1
    for (int np = 0; np < 8; np++) {
        uint32_t z[2][2][2];
#pragma unroll
        for (int m = 0; m < 2; m++)
#pragma unroll
            for (int n = 0; n < 2; n++) { z[m][n][0] = 0u; z[m][n][1] = 0u; }
#pragma unroll
        for (int kt = 0; kt < 8; kt++) {
            uint32_t wb[4];
            ldsm_x4(mrow(sb + SMEM_W1, np * 16 + (lane & 15),
                         kt * 2 + (lane >> 4)), wb);
            mma_h(z[0][0], ya[0][kt], wb[0], wb[2]);
            mma_h(z[0][1], ya[0][kt], wb[1], wb[3]);
            mma_h(z[1][0], ya[1][kt], wb[0], wb[2]);
            mma_h(z[1][1], ya[1][kt], wb[1], wb[3]);
        }
#pragma unroll
        for (int n = 0; n < 2; n++) {
            int c = (2 * np + n) * 8 + c4;
#pragma unroll
            for (int m = 0; m < 2; m++) {
                int r = tm + m * 16 + g;
                float2 lo = up2h(z[m][n][0]);  // rows r:   cols c, c+1
                float2 hi = up2h(z[m][n][1]);  // rows r+8
                zsf[c * 260 + r]           = lo.x;
                zsf[(c + 1) * 260 + r]     = lo.y;
                zsf[c * 260 + r + 8]       = hi.x;
                zsf[(c + 1) * 260 + r + 8] = hi.y;
            }
        }
    }
    __syncthreads();

    // ---- epilogue: out = x + z + bo (coalesced float4, exact residual) ----
#pragma unroll 4
    for (int i = 0; i < 32; i++) {
        int it = tid + i * 256;
        int c = it >> 6, q = it & 63;
        int sh = q >> 2, sw4 = (q & 3) << 2;
        int l = sh * 16 + sw4;
        int ga = xbase + c * 262144 + sh * 512 + sw4;
        float4 xv = *reinterpret_cast<const float4*>(x + ga);
        float4 zv = *reinterpret_cast<const float4*>(zsf + c * 260 + l);
        float bc = __ldg(bo + c);
        float4 ov;
        ov.x = xv.x + zv.x + bc; ov.y = xv.y + zv.y + bc;
        ov.z = xv.z + zv.z + bc; ov.w = xv.w + zv.w + bc;
        *reinterpret_cast<float4*>(out + ga) = ov;
    }
}

extern "C" void kernel_launch(void* const* d_in, const int* in_sizes, int n_in,
                              void* d_out, int out_size) {
    const float* x  = (const float*)d_in[0];
    const float* Wq = (const float*)d_in[1];
    const float* bq = (const float*)d_in[2];
    const float* Wk = (const float*)d_in[3];
    const float* bk = (const float*)d_in[4];
    const float* Wv = (const float*)d_in[5];
    const float* bv = (const float*)d_in[6];
    const float* Wo = (const float*)d_in[7];
    const float* bo = (const float*)d_in[8];
    float* out = (float*)d_out;

    prep_weights<<<32, 256>>>(Wq, Wk, Wv, Wo, bq, bk, bv);

    cudaFuncSetAttribute(PatchAttention_24902220382269_kernel,
                         cudaFuncAttributeMaxDynamicSharedMemorySize, SMEM_TOTAL);
    PatchAttention_24902220382269_kernel<<<2048, 256, SMEM_TOTAL>>>(x, bo, out);
}

// round 16
// speedup vs baseline: 1.3617x; 1.0833x over previous
#include <cuda_runtime.h>
#include <cuda_fp16.h>
#include <stdint.h>

// PatchAttention, R16: V/O projections folded (Wz = Wo@Wv, bz = Wo@bv + bo):
//   out = x + (exp(S)@P)/rowsum @ Wz^T + bz,  S = (P Wq^T)(P Wk^T)^T * 1/tau
// One CTA per patch (2048 x 256 thr, 8 warps x 32 rows), f16 mma accum,
// pipelined attention, ex2.approx.f16x2 softmax (log2e/tau folded into Wq).

#define SMEM_P     0u        // raw patch P [256][128] f16 swizzled (64 KB)
#define SMEM_K     65536u    // K [256][128] f16 swizzled (64 KB)
#define SMEM_W0    131072u   // Wq stage (32 KB)
#define SMEM_W1    163840u   // Wk stage, later Wz (32 KB)
#define SMEM_Z     0u        // Z [128][260] f32 (overlays P,K,W0-head)
#define SMEM_TOTAL 196608u

#define QSCALE ((float)(1.4426950408889634 / 11.313708498984761))  // log2e/sqrt(128)

__device__ uint32_t gW[3][8192];   // f16x2 swizzled: Wq*QSCALE, Wk, Wz
__device__ uint32_t gB[2][64];     // f16x2 col-pair biases: bq*QSCALE, bk
__device__ float    gWzF[16384];   // fp32 Wz = Wo @ Wv
__device__ float    gBz[128];      // fp32 bz = Wo @ bv + bo

__device__ __forceinline__ uint32_t pack2h(float lo, float hi) {
    uint32_t r;
    asm("cvt.rn.f16x2.f32 %0, %1, %2;" : "=r"(r) : "f"(hi), "f"(lo));
    return r;
}
__device__ __forceinline__ float2 up2h(uint32_t u) {
    __half2 h = *reinterpret_cast<__half2*>(&u);
    return __half22float2(h);
}
__device__ __forceinline__ uint16_t h16(float v) {
    uint16_t r;
    asm("cvt.rn.f16.f32 %0, %1;" : "=h"(r) : "f"(v));
    return r;
}
__device__ __forceinline__ uint32_t hadd2u(uint32_t a, uint32_t b) {
    uint32_t d; asm("add.rn.f16x2 %0, %1, %2;" : "=r"(d) : "r"(a), "r"(b)); return d;
}
__device__ __forceinline__ uint32_t hmul2u(uint32_t a, uint32_t b) {
    uint32_t d; asm("mul.rn.f16x2 %0, %1, %2;" : "=r"(d) : "r"(a), "r"(b)); return d;
}
__device__ __forceinline__ uint32_t ex2u(uint32_t a) {
    uint32_t d; asm("ex2.approx.f16x2 %0, %1;" : "=r"(d) : "r"(a)); return d;
}
__device__ __forceinline__ uint32_t mrow(uint32_t base, int row, int chunk) {
    return base + (uint32_t)row * 256u + (uint32_t)(((chunk ^ (row & 7)) << 4));
}
__device__ __forceinline__ void ldsm_x4(uint32_t a, uint32_t r[4]) {
    asm volatile("ldmatrix.sync.aligned.m8n8.x4.shared.b16 {%0,%1,%2,%3}, [%4];"
                 : "=r"(r[0]), "=r"(r[1]), "=r"(r[2]), "=r"(r[3]) : "r"(a));
}
__device__ __forceinline__ void ldsm_x4t(uint32_t a, uint32_t r[4]) {
    asm volatile("ldmatrix.sync.aligned.m8n8.x4.trans.shared.b16 {%0,%1,%2,%3}, [%4];"
                 : "=r"(r[0]), "=r"(r[1]), "=r"(r[2]), "=r"(r[3]) : "r"(a));
}
__device__ __forceinline__ void mma_h(uint32_t c[2], const uint32_t a[4],
                                      uint32_t b0, uint32_t b1) {
    asm volatile(
        "mma.sync.aligned.m16n8k16.row.col.f16.f16.f16.f16 "
        "{%0,%1},{%2,%3,%4,%5},{%6,%7},{%0,%1};"
        : "+r"(c[0]), "+r"(c[1])
        : "r"(a[0]), "r"(a[1]), "r"(a[2]), "r"(a[3]), "r"(b0), "r"(b1));
}
__device__ __forceinline__ void cp16(uint32_t s, const void* g) {
    asm volatile("cp.async.ca.shared.global [%0], [%1], 16;" :: "r"(s), "l"(g));
}
__device__ __forceinline__ void cp_commit() { asm volatile("cp.async.commit_group;"); }
__device__ __forceinline__ void cp_wait_all() { asm volatile("cp.async.wait_group 0;"); }

// ---- prep 1: Wz = Wo @ Wv (fp32), bz = Wo @ bv + bo -------------------------
__global__ void prep_wz(const float* __restrict__ Wo, const float* __restrict__ Wv,
                        const float* __restrict__ bv, const float* __restrict__ bo) {
    int i = blockIdx.x, j = threadIdx.x;   // 128 x 128
    float s = 0.f;
#pragma unroll 8
    for (int k = 0; k < 128; k++) s = fmaf(Wo[i * 128 + k], Wv[k * 128 + j], s);
    gWzF[i * 128 + j] = s;
    if (j == 0) {
        float b = bo[i];
        for (int k = 0; k < 128; k++) b = fmaf(Wo[i * 128 + k], bv[k], b);
        gBz[i] = b;
    }
}

// ---- prep 2: pack Wq*QSCALE, Wk, Wz -> f16x2 swizzled; biases ---------------
__global__ void prep_pack(const float* __restrict__ Wq, const float* __restrict__ Wk,
                          const float* __restrict__ bq, const float* __restrict__ bk) {
    int t = blockIdx.x * 256 + threadIdx.x;  // 8192 threads, one slot per weight
    int d = t >> 6, j = t & 63;
    uint32_t slot = (uint32_t)(d * 64 + (((j >> 2) ^ (d & 7)) << 2) + (j & 3));
    float2 vq = *reinterpret_cast<const float2*>(Wq + d * 128 + 2 * j);
    gW[0][slot] = pack2h(vq.x * QSCALE, vq.y * QSCALE);
    float2 vk = *reinterpret_cast<const float2*>(Wk + d * 128 + 2 * j);
    gW[1][slot] = pack2h(vk.x, vk.y);
    float2 vz = *reinterpret_cast<const float2*>(gWzF + d * 128 + 2 * j);
    gW[2][slot] = pack2h(vz.x, vz.y);
    if (blockIdx.x == 0 && threadIdx.x < 128) {
        int w = threadIdx.x >> 6, jj = threadIdx.x & 63;
        const float* bs = w ? bk : bq;
        float sc = w ? 1.f : QSCALE;
        gB[w][jj] = pack2h(bs[2 * jj] * sc, bs[2 * jj + 1] * sc);
    }
}

__global__ void __launch_bounds__(256, 1)
PatchAttention_24902220382269_kernel(
    const float* __restrict__ x, float* __restrict__ out)
{
    extern __shared__ char smem[];
    const uint32_t sb = (uint32_t)__cvta_generic_to_shared(smem);
    const int tid  = threadIdx.x;
    const int lane = tid & 31;
    const int warp = tid >> 5;
    const int tm   = warp * 32;

    const int pid   = blockIdx.x;
    const int xbase = (pid >> 10) * 33554432 + ((pid >> 5) & 31) * 8192 + (pid & 31) * 16;

    // stage Wq, Wk
#pragma unroll
    for (int i = 0; i < 8; i++) {
        int ch = tid + i * 256;
        cp16(sb + SMEM_W0 + ch * 16, (const char*)gW[0] + ch * 16);
        cp16(sb + SMEM_W1 + ch * 16, (const char*)gW[1] + ch * 16);
    }
    cp_commit();

    // patch load: x -> P token-major f16 swizzled
#pragma unroll 4
    for (int i = 0; i < 32; i++) {
        int it = tid + i * 256;
        int c = it >> 6, q = it & 63;
        int sh = q >> 2, sw4 = (q & 3) << 2;
        float4 v4 = *reinterpret_cast<const float4*>(
            x + xbase + c * 262144 + sh * 512 + sw4);
        int l = sh * 16 + sw4;
        float vv[4] = {v4.x, v4.y, v4.z, v4.w};
#pragma unroll
        for (int j = 0; j < 4; j++) {
            int row = l + j;
            *reinterpret_cast<uint16_t*>(smem + SMEM_P + (uint32_t)row * 256u +
                (uint32_t)((((c >> 3) ^ (row & 7)) << 4) + (c & 7) * 2)) = h16(vv[j]);
        }
    }
    cp_wait_all();
    __syncthreads();

    const int g = lane >> 2;

    // ---- merged Q+K projection (one A pass): Q -> regs, K -> SMEM_K --------
    uint32_t qa[2][8][4];
    {
        uint32_t accQ[16][2][2], accK[16][2][2];
#pragma unroll
        for (int nt = 0; nt < 16; nt++)
#pragma unroll
            for (int m = 0; m < 2; m++) {
                accQ[nt][m][0] = accQ[nt][m][1] = 0u;
                accK[nt][m][0] = accK[nt][m][1] = 0u;
            }
#pragma unroll
        for (int kt = 0; kt < 8; kt++) {
            uint32_t a0[4], a1[4];
            ldsm_x4(mrow(sb + SMEM_P, tm +      (lane & 15), kt * 2 + (lane >> 4)), a0);
            ldsm_x4(mrow(sb + SMEM_P, tm + 16 + (lane & 15), kt * 2 + (lane >> 4)), a1);
#pragma unroll
            for (int np = 0; np < 8; np++) {
                uint32_t wb[4];
                ldsm_x4(mrow(sb + SMEM_W0, np * 16 + (lane & 15),
                             kt * 2 + (lane >> 4)), wb);
                mma_h(accQ[2*np][0],   a0, wb[0], wb[2]);
                mma_h(accQ[2*np+1][0], a0, wb[1], wb[3]);
                mma_h(accQ[2*np][1],   a1, wb[0], wb[2]);
                mma_h(accQ[2*np+1][1], a1, wb[1], wb[3]);
            }
#pragma unroll
            for (int np = 0; np < 8; np++) {
                uint32_t wb[4];
                ldsm_x4(mrow(sb + SMEM_W1, np * 16 + (lane & 15),
                             kt * 2 + (lane >> 4)), wb);
                mma_h(accK[2*np][0],   a0, wb[0], wb[2]);
                mma_h(accK[2*np+1][0], a0, wb[1], wb[3]);
                mma_h(accK[2*np][1],   a1, wb[0], wb[2]);
                mma_h(accK[2*np+1][1], a1, wb[1], wb[3]);
            }
        }
        // Q epilogue -> registers (C-frag == A-frag packing)
#pragma unroll
        for (int kt = 0; kt < 8; kt++) {
            uint32_t b0 = __ldg(&gB[0][8 * kt +     (lane & 3)]);
            uint32_t b1 = __ldg(&gB[0][8 * kt + 4 + (lane & 3)]);
#pragma unroll
            for (int m = 0; m < 2; m++) {
                qa[m][kt][0] = hadd2u(accQ[2*kt][m][0],   b0);
                qa[m][kt][1] = hadd2u(accQ[2*kt][m][1],   b0);
                qa[m][kt][2] = hadd2u(accQ[2*kt+1][m][0], b1);
                qa[m][kt][3] = hadd2u(accQ[2*kt+1][m][1], b1);
            }
        }
        // K epilogue -> SMEM_K (swizzled f16)
        const int c4 = (lane & 3) << 1;
#pragma unroll
        for (int nt = 0; nt < 16; nt++) {
            uint32_t bias2 = __ldg(&gB[1][nt * 4 + (lane & 3)]);
#pragma unroll
            for (int m = 0; m < 2; m++) {
                int r = tm + m * 16 + g;
                uint32_t cb = (uint32_t)(((nt ^ (r & 7)) << 4) + c4 * 2);
                *reinterpret_cast<uint32_t*>(smem + SMEM_K + (uint32_t)r * 256u + cb) =
                    hadd2u(accK[nt][m][0], bias2);
                *reinterpret_cast<uint32_t*>(smem + SMEM_K + (uint32_t)(r + 8) * 256u + cb) =
                    hadd2u(accK[nt][m][1], bias2);
            }
        }
    }
    __syncthreads();

    // stage Wz into W1 (Wk weights consumed above)
#pragma unroll
    for (int i = 0; i < 8; i++) {
        int ch = tid + i * 256;
        cp16(sb + SMEM_W1 + ch * 16, (const char*)gW[2] + ch * 16);
    }
    cp_commit();

    // ---- attention (pipelined): T = exp(Q K^T) @ P ----
    uint32_t yacc[2][16][2];
#pragma unroll
    for (int m = 0; m < 2; m++)
#pragma unroll
        for (int nt = 0; nt < 16; nt++) { yacc[m][nt][0] = 0u; yacc[m][nt][1] = 0u; }
    float rs[2][2] = {{0.f, 0.f}, {0.f, 0.f}};

    auto computeS = [&](int k0, uint32_t s[8]) {
#pragma unroll
        for (int i = 0; i < 8; i++) s[i] = 0u;
#pragma unroll
        for (int kt = 0; kt < 8; kt++) {
            uint32_t kb[4];
            ldsm_x4(mrow(sb + SMEM_K, k0 + (lane & 15), kt * 2 + (lane >> 4)), kb);
            mma_h(s + 0, qa[0][kt], kb[0], kb[2]);
            mma_h(s + 2, qa[0][kt], kb[1], kb[3]);
            mma_h(s + 4, qa[1][kt], kb[0], kb[2]);
            mma_h(s + 6, qa[1][kt], kb[1], kb[3]);
        }
    };

    uint32_t scur[8];
    computeS(0, scur);
#pragma unroll 1
    for (int kc = 0; kc < 16; kc++) {
        uint32_t pa[2][4];
#pragma unroll
        for (int m = 0; m < 2; m++) {
            pa[m][0] = ex2u(scur[m*4 + 0]);
            pa[m][1] = ex2u(scur[m*4 + 1]);
            pa[m][2] = ex2u(scur[m*4 + 2]);
            pa[m][3] = ex2u(scur[m*4 + 3]);
            float2 t0 = up2h(hadd2u(pa[m][0], pa[m][2]));
            float2 t1 = up2h(hadd2u(pa[m][1], pa[m][3]));
            rs[m][0] += t0.x + t0.y;
            rs[m][1] += t1.x + t1.y;
        }
        uint32_t snxt[8];
        if (kc < 15) computeS((kc + 1) * 16, snxt);
#pragma unroll
        for (int np = 0; np < 8; np++) {
            uint32_t vb[4];
            ldsm_x4t(mrow(sb + SMEM_P, kc * 16 + (lane & 15), np * 2 + (lane >> 4)), vb);
            mma_h(yacc[0][2*np],   pa[0], vb[0], vb[1]);
            mma_h(yacc[0][2*np+1], pa[0], vb[2], vb[3]);
            mma_h(yacc[1][2*np],   pa[1], vb[0], vb[1]);
            mma_h(yacc[1][2*np+1], pa[1], vb[2], vb[3]);
        }
        if (kc < 15) {
#pragma unroll
            for (int i = 0; i < 8; i++) scur[i] = snxt[i];
        }
    }
#pragma unroll
    for (int m = 0; m < 2; m++)
#pragma unroll
        for (int h = 0; h < 2; h++) {
            float v = rs[m][h];
            v += __shfl_xor_sync(0xffffffffu, v, 1);
            v += __shfl_xor_sync(0xffffffffu, v, 2);
            rs[m][h] = 1.f / v;
        }

    // normalize T -> f16 A frags
    uint32_t ya[2][8][4];
#pragma unroll
    for (int m = 0; m < 2; m++) {
        uint32_t rr0 = pack2h(rs[m][0], rs[m][0]);
        uint32_t rr1 = pack2h(rs[m][1], rs[m][1]);
#pragma unroll
        for (int kt = 0; kt < 8; kt++) {
            ya[m][kt][0] = hmul2u(yacc[m][2*kt][0],   rr0);
            ya[m][kt][1] = hmul2u(yacc[m][2*kt][1],   rr1);
            ya[m][kt][2] = hmul2u(yacc[m][2*kt+1][0], rr0);
            ya[m][kt][3] = hmul2u(yacc[m][2*kt+1][1], rr1);
        }
    }
    cp_wait_all();       // Wz staged
    __syncthreads();     // all P/K reads done; Z may overlay

    // ---- Z = (T/rs) @ Wz^T, fp32 staged in SMEM (stride 260) ----
    float* zsf = reinterpret_cast<float*>(smem + SMEM_Z);
    const int c4 = (lane & 3) << 1;
#pragma unroll 1
    for (int np = 0; np < 8; np++) {
        uint32_t z[2][2][2];
#pragma unroll
        for (int m = 0; m < 2; m++)
#pragma unroll
            for (int n = 0; n < 2; n++) { z[m][n][0] = 0u; z[m][n][1] = 0u; }
#pragma unroll
        for (int kt = 0; kt < 8; kt++) {
            uint32_t wb[4];
            ldsm_x4(mrow(sb + SMEM_W1, np * 16 + (lane & 15),
                         kt * 2 + (lane >> 4)), wb);
            mma_h(z[0][0], ya[0][kt], wb[0], wb[2]);
            mma_h(z[0][1], ya[0][kt], wb[1], wb[3]);
            mma_h(z[1][0], ya[1][kt], wb[0], wb[2]);
            mma_h(z[1][1], ya[1][kt], wb[1], wb[3]);
        }
#pragma unroll
        for (int n = 0; n < 2; n++) {
            int c = (2 * np + n) * 8 + c4;
#pragma unroll
            for (int m = 0; m < 2; m++) {
                int r = tm + m * 16 + g;
                float2 lo = up2h(z[m][n][0]);
                float2 hi = up2h(z[m][n][1]);
                zsf[c * 260 + r]           = lo.x;
                zsf[(c + 1) * 260 + r]     = lo.y;
                zsf[c * 260 + r + 8]       = hi.x;
                zsf[(c + 1) * 260 + r + 8] = hi.y;
            }
        }
    }
    __syncthreads();

    // ---- epilogue: out = x + z + bz (exact fp32 residual) ----
#pragma unroll 4
    for (int i = 0; i < 32; i++) {
        int it = tid + i * 256;
        int c = it >> 6, q = it & 63;
        int sh = q >> 2, sw4 = (q & 3) << 2;
        int l = sh * 16 + sw4;
        int ga = xbase + c * 262144 + sh * 512 + sw4;
        float4 xv = *reinterpret_cast<const float4*>(x + ga);
        float4 zv = *reinterpret_cast<const float4*>(zsf + c * 260 + l);
        float bc = __ldg(&gBz[c]);
        float4 ov;
        ov.x = xv.x + zv.x + bc; ov.y = xv.y + zv.y + bc;
        ov.z = xv.z + zv.z + bc; ov.w = xv.w + zv.w + bc;
        *reinterpret_cast<float4*>(out + ga) = ov;
    }
}

extern "C" void kernel_launch(void* const* d_in, const int* in_sizes, int n_in,
                              void* d_out, int out_size) {
    const float* x  = (const float*)d_in[0];
    const float* Wq = (const float*)d_in[1];
    const float* bq = (const float*)d_in[2];
    const float* Wk = (const float*)d_in[3];
    const float* bk = (const float*)d_in[4];
    const float* Wv = (const float*)d_in[5];
    const float* bv = (const float*)d_in[6];
    const float* Wo = (const float*)d_in[7];
    const float* bo = (const float*)d_in[8];
    float* out = (float*)d_out;

    prep_wz<<<128, 128>>>(Wo, Wv, bv, bo);
    prep_pack<<<32, 256>>>(Wq, Wk, bq, bk);

    cudaFuncSetAttribute(PatchAttention_24902220382269_kernel,
                         cudaFuncAttributeMaxDynamicSharedMemorySize, SMEM_TOTAL);
    PatchAttention_24902220382269_kernel<<<2048, 256, SMEM_TOTAL>>>(x, out);
}